// round 12
// baseline (speedup 1.0000x reference)
#include <cuda_runtime.h>
#include <cuda_bf16.h>
#include <cstdint>
#include <cstring>

#define B_    256
#define IND   2048
#define D_    128
#define KQ    65536
#define LD_   65569              /* 1 + K + S1 + S2 */
#define INV_T (1.0f/0.07f)
#define SPLITK 8
#define NC64  1024               /* 64-wide chunks per row */
#define NC128 512                /* 128-wide chunks */
#define CSTRIDE 74               /* grid.x for k2p (74*2 = 148 = one wave) */

// ---------------- device scratch (no allocation allowed) -------------------
__device__ __align__(16) float g_pq[SPLITK * B_ * D_];
__device__ __align__(16) float g_pk[SPLITK * B_ * D_];
__device__ __align__(16) float g_outq[B_ * D_];          // normalized out_q
__device__ __align__(16) unsigned short g_ah[B_ * D_];   // bf16 hi of out_q
__device__ __align__(16) unsigned short g_al[B_ * D_];   // bf16 lo of out_q
__device__ __align__(16) unsigned g_cmaxu[B_ * NC64];    // fkey of per-64chunk max
__device__ int g_hard[B_ * 32];
__device__ unsigned g_dummy[1];

__device__ __forceinline__ unsigned fkey(float f) {
    unsigned u = __float_as_uint(f);
    return (u >> 31) ? ~u : (u | 0x80000000u);
}
__device__ __forceinline__ uint32_t smem_u32(const void* p) {
    uint32_t a;
    asm("{ .reg .u64 t; cvta.to.shared.u64 t, %1; cvt.u32.u64 %0, t; }" : "=r"(a) : "l"(p));
    return a;
}
__device__ __forceinline__ void ldsm4(uint32_t* r, uint32_t a) {
    asm volatile("ldmatrix.sync.aligned.m8n8.x4.shared.b16 {%0,%1,%2,%3}, [%4];"
                 : "=r"(r[0]), "=r"(r[1]), "=r"(r[2]), "=r"(r[3]) : "r"(a));
}
__device__ __forceinline__ void mma16816(float* c, const uint32_t* a, uint32_t b0, uint32_t b1) {
    asm volatile(
        "mma.sync.aligned.m16n8k16.row.col.f32.bf16.bf16.f32 "
        "{%0,%1,%2,%3}, {%4,%5,%6,%7}, {%8,%9}, {%0,%1,%2,%3};"
        : "+f"(c[0]), "+f"(c[1]), "+f"(c[2]), "+f"(c[3])
        : "r"(a[0]), "r"(a[1]), "r"(a[2]), "r"(a[3]), "r"(b0), "r"(b1));
}

// ---------------- k1: encoder GEMMs, split-K=8 -----------------------------
__global__ void k1_gemm(const float* __restrict__ q, const float* __restrict__ kk,
                        const float* __restrict__ Wq, const float* __restrict__ Wk) {
    __shared__ float qs[16][32];
    __shared__ float ks[16][32];
    const float C0 = 0.999f, C1 = 1.0f - 0.999f;
    int t = threadIdx.x;
    int c = t & 127, h = t >> 7;
    int rb = blockIdx.x * 16;
    int k0 = blockIdx.y * (IND / SPLITK);

    float aq[8], ak[8];
    #pragma unroll
    for (int j = 0; j < 8; j++) { aq[j] = 0.f; ak[j] = 0.f; }

    for (int kc = 0; kc < IND / SPLITK; kc += 32) {
        __syncthreads();
        #pragma unroll
        for (int e = 0; e < 2; e++) {
            int id = t + e * 256;
            int r = id >> 5, i = id & 31;
            qs[r][i] = q [(size_t)(rb + r) * IND + k0 + kc + i];
            ks[r][i] = kk[(size_t)(rb + r) * IND + k0 + kc + i];
        }
        __syncthreads();
        #pragma unroll
        for (int u0 = 0; u0 < 32; u0 += 8) {
            float wq[8], wm[8];
            #pragma unroll
            for (int u = 0; u < 8; u++) {
                float a = Wq[(size_t)(k0 + kc + u0 + u) * D_ + c];
                float b = Wk[(size_t)(k0 + kc + u0 + u) * D_ + c];
                wq[u] = a;
                wm[u] = C0 * b + C1 * a;
            }
            #pragma unroll
            for (int u = 0; u < 8; u++)
                #pragma unroll
                for (int j = 0; j < 8; j++) {
                    aq[j] = fmaf(qs[h * 8 + j][u0 + u], wq[u], aq[j]);
                    ak[j] = fmaf(ks[h * 8 + j][u0 + u], wm[u], ak[j]);
                }
        }
    }
    int sk = blockIdx.y;
    #pragma unroll
    for (int j = 0; j < 8; j++) {
        int r = rb + h * 8 + j;
        g_pq[((size_t)sk * B_ + r) * D_ + c] = aq[j];
        g_pk[((size_t)sk * B_ + r) * D_ + c] = ak[j];
    }
}

// ---------------- k1b: reduce, normalize, pos logit, bf16 hi/lo split ------
__global__ void k1b_norm(float* __restrict__ out) {
    int t = threadIdx.x, lane = t & 31, w = t >> 5;
    int rb = blockIdx.x * 32;
    for (int rr = 0; rr < 4; rr++) {
        int r = rb + rr * 8 + w;
        float4 q4 = make_float4(0.f, 0.f, 0.f, 0.f);
        float4 k4 = make_float4(0.f, 0.f, 0.f, 0.f);
        #pragma unroll
        for (int s = 0; s < SPLITK; s++) {
            float4 a = *(const float4*)&g_pq[((size_t)s * B_ + r) * D_ + lane * 4];
            float4 b = *(const float4*)&g_pk[((size_t)s * B_ + r) * D_ + lane * 4];
            q4.x += a.x; q4.y += a.y; q4.z += a.z; q4.w += a.w;
            k4.x += b.x; k4.y += b.y; k4.z += b.z; k4.w += b.w;
        }
        float s1 = q4.x*q4.x + q4.y*q4.y + q4.z*q4.z + q4.w*q4.w;
        float s2 = k4.x*k4.x + k4.y*k4.y + k4.z*k4.z + k4.w*k4.w;
        float s3 = q4.x*k4.x + q4.y*k4.y + q4.z*k4.z + q4.w*k4.w;
        #pragma unroll
        for (int o = 16; o; o >>= 1) {
            s1 += __shfl_xor_sync(0xffffffffu, s1, o);
            s2 += __shfl_xor_sync(0xffffffffu, s2, o);
            s3 += __shfl_xor_sync(0xffffffffu, s3, o);
        }
        float invq = 1.f / fmaxf(sqrtf(s1), 1e-12f);
        float invk = 1.f / fmaxf(sqrtf(s2), 1e-12f);
        float vs[4] = {q4.x * invq, q4.y * invq, q4.z * invq, q4.w * invq};
        *(float4*)&g_outq[(size_t)r * D_ + lane * 4] = make_float4(vs[0], vs[1], vs[2], vs[3]);
        unsigned hs[4], ls[4];
        #pragma unroll
        for (int j = 0; j < 4; j++) {
            __nv_bfloat16 hb = __float2bfloat16_rn(vs[j]);
            float lo = vs[j] - __bfloat162float(hb);
            hs[j] = (unsigned)__bfloat16_as_ushort(hb);
            ls[j] = (unsigned)__bfloat16_as_ushort(__float2bfloat16_rn(lo));
        }
        ((uint2*)g_ah)[r * 32 + lane] = make_uint2(hs[0] | (hs[1] << 16), hs[2] | (hs[3] << 16));
        ((uint2*)g_al)[r * 32 + lane] = make_uint2(ls[0] | (ls[1] << 16), ls[2] | (ls[3] << 16));
        if (lane == 0) out[(size_t)r * LD_] = s3 * invq * invk * INV_T;
    }
}

// ---------------- k_pos3: no-op spacer so ncu (-s 5) captures k2p ----------
__global__ void k_pos3() { if (threadIdx.x == 0) g_dummy[0] = 0u; }

// ---------------- k2p: pipelined HMMA bf16 3-term GEMM ---------------------
// grid (74, 2): one full wave, each block loops ~7 chunks of 128 N-cols.
// Block 256 thr, tile 128x128; warp grid 2(M)x4(N), warp tile 64x32.
// A (out_q hi/lo) resident in smem; B double-buffered, prefetch interleaved
// into the mma k-loop. Epilogue uses SCALAR stores (LD_ is odd -> odd rows
// have 4B-aligned-only addresses; float2 stores trap).
#define A_H 0
#define A_L 32768
#define K2P_SMEM (65536 + 4*32768)   /* A 64KB + B 2 stages x 64KB = 192KB */

__global__ void __launch_bounds__(256, 1)
k2p_gemm(const float* __restrict__ queue, float* __restrict__ out) {
    extern __shared__ __align__(16) char smc[];
    __shared__ unsigned cmbuf[256];          // 128 rows x 2 halves
    const int BHO[2] = {65536, 131072};
    const int BLO[2] = {98304, 163840};
    int t = threadIdx.x, lane = t & 31, w = t >> 5;
    int wm = w & 1, wn = w >> 1;
    int mt = blockIdx.y;
    int l15 = lane & 15, sx = lane & 7, khalf = lane >> 4;

    // ---- resident A (128 rows of g_ah/g_al), swizzled ----
    #pragma unroll
    for (int it = 0; it < 8; it++) {
        int cid = t + it * 256;              // 2048 16B chunks per half
        int r = cid >> 4, c = cid & 15;
        uint32_t dst = (uint32_t)(r * 256 + ((c ^ (r & 7)) << 4));
        int gi = (mt * 128 + r) * 16 + c;
        *(uint4*)(smc + A_H + dst) = ((const uint4*)g_ah)[gi];
        *(uint4*)(smc + A_L + dst) = ((const uint4*)g_al)[gi];
    }

    // ---- synchronous fill of stage 0 for first chunk ----
    int ci0 = blockIdx.x;
    {
        int nb = ci0 * 128;
        #pragma unroll
        for (int it = 0; it < 16; it++) {
            int cid = t + it * 256;          // 4096 float4 (128 n x 32)
            int n = cid >> 5, c4 = cid & 31;
            float4 v = *(const float4*)(queue + (size_t)(nb + n) * D_ + c4 * 4);
            float vv[4] = {v.x, v.y, v.z, v.w};
            unsigned hp[4], lp[4];
            #pragma unroll
            for (int j = 0; j < 4; j++) {
                __nv_bfloat16 hb = __float2bfloat16_rn(vv[j]);
                float lo = vv[j] - __bfloat162float(hb);
                hp[j] = (unsigned)__bfloat16_as_ushort(hb);
                lp[j] = (unsigned)__bfloat16_as_ushort(__float2bfloat16_rn(lo));
            }
            int c = c4 >> 1;
            uint32_t dst = (uint32_t)(n * 256 + ((c ^ (n & 7)) << 4) + (c4 & 1) * 8);
            *(uint2*)(smc + BHO[0] + dst) = make_uint2(hp[0] | (hp[1] << 16), hp[2] | (hp[3] << 16));
            *(uint2*)(smc + BLO[0] + dst) = make_uint2(lp[0] | (lp[1] << 16), lp[2] | (lp[3] << 16));
        }
    }

    int cur = 0;
    for (int ci = ci0; ci < NC128; ci += CSTRIDE) {
        int nb = ci * 128;
        int cn = ci + CSTRIDE;
        bool hn = cn < NC128;
        int nbn = cn * 128;
        int nxt = cur ^ 1;
        __syncthreads();                     // stage[cur] ready; cmbuf free
        if (t < 256) cmbuf[t] = 0u;

        uint32_t bh = smem_u32(smc + BHO[cur]);
        uint32_t bl = smem_u32(smc + BLO[cur]);
        uint32_t ah = smem_u32(smc + A_H);
        uint32_t al = smem_u32(smc + A_L);

        float acc[4][4][4];
        #pragma unroll
        for (int mi = 0; mi < 4; mi++)
            #pragma unroll
            for (int ni = 0; ni < 4; ni++)
                #pragma unroll
                for (int j = 0; j < 4; j++) acc[mi][ni][j] = 0.f;

        float4 pf[4];
        int pj = -1;                         // batch currently in pf

        #pragma unroll
        for (int ks = 0; ks < 8; ks++) {
            if (hn && (ks & 1) == 0) {
                // flush previous batch, issue next (4 float4 per batch)
                if (pj >= 0) {
                    #pragma unroll
                    for (int e = 0; e < 4; e++) {
                        int cid = t + (pj * 4 + e) * 256;
                        int n = cid >> 5, c4 = cid & 31;
                        float vv[4] = {pf[e].x, pf[e].y, pf[e].z, pf[e].w};
                        unsigned hp[4], lp[4];
                        #pragma unroll
                        for (int j = 0; j < 4; j++) {
                            __nv_bfloat16 hb = __float2bfloat16_rn(vv[j]);
                            float lo = vv[j] - __bfloat162float(hb);
                            hp[j] = (unsigned)__bfloat16_as_ushort(hb);
                            lp[j] = (unsigned)__bfloat16_as_ushort(__float2bfloat16_rn(lo));
                        }
                        int c = c4 >> 1;
                        uint32_t dst = (uint32_t)(n * 256 + ((c ^ (n & 7)) << 4) + (c4 & 1) * 8);
                        *(uint2*)(smc + BHO[nxt] + dst) = make_uint2(hp[0] | (hp[1] << 16), hp[2] | (hp[3] << 16));
                        *(uint2*)(smc + BLO[nxt] + dst) = make_uint2(lp[0] | (lp[1] << 16), lp[2] | (lp[3] << 16));
                    }
                }
                pj = ks >> 1;
                #pragma unroll
                for (int e = 0; e < 4; e++) {
                    int cid = t + (pj * 4 + e) * 256;
                    int n = cid >> 5, c4 = cid & 31;
                    pf[e] = *(const float4*)(queue + (size_t)(nbn + n) * D_ + c4 * 4);
                }
            }
            int kc = ks * 2 + khalf;
            uint32_t Bh[2][4], Bl[2][4];
            #pragma unroll
            for (int bi = 0; bi < 2; bi++) {
                uint32_t off = (uint32_t)((wn * 32 + bi * 16 + l15) * 256 + ((kc ^ sx) << 4));
                ldsm4(Bh[bi], bh + off);
                ldsm4(Bl[bi], bl + off);
            }
            #pragma unroll
            for (int mi = 0; mi < 4; mi++) {
                uint32_t Ah[4], Al[4];
                uint32_t off = (uint32_t)((wm * 64 + mi * 16 + l15) * 256 + ((kc ^ sx) << 4));
                ldsm4(Ah, ah + off);
                ldsm4(Al, al + off);
                #pragma unroll
                for (int ni = 0; ni < 4; ni++) {
                    int bi = ni >> 1, j = ni & 1;
                    mma16816(acc[mi][ni], Ah, Bh[bi][j], Bh[bi][j + 2]);
                    mma16816(acc[mi][ni], Ah, Bl[bi][j], Bl[bi][j + 2]);
                    mma16816(acc[mi][ni], Al, Bh[bi][j], Bh[bi][j + 2]);
                }
            }
        }
        // flush last prefetch batch
        if (hn && pj >= 0) {
            #pragma unroll
            for (int e = 0; e < 4; e++) {
                int cid = t + (pj * 4 + e) * 256;
                int n = cid >> 5, c4 = cid & 31;
                float vv[4] = {pf[e].x, pf[e].y, pf[e].z, pf[e].w};
                unsigned hp[4], lp[4];
                #pragma unroll
                for (int j = 0; j < 4; j++) {
                    __nv_bfloat16 hb = __float2bfloat16_rn(vv[j]);
                    float lo = vv[j] - __bfloat162float(hb);
                    hp[j] = (unsigned)__bfloat16_as_ushort(hb);
                    lp[j] = (unsigned)__bfloat16_as_ushort(__float2bfloat16_rn(lo));
                }
                int c = c4 >> 1;
                uint32_t dst = (uint32_t)(n * 256 + ((c ^ (n & 7)) << 4) + (c4 & 1) * 8);
                *(uint2*)(smc + BHO[nxt] + dst) = make_uint2(hp[0] | (hp[1] << 16), hp[2] | (hp[3] << 16));
                *(uint2*)(smc + BLO[nxt] + dst) = make_uint2(lp[0] | (lp[1] << 16), lp[2] | (lp[3] << 16));
            }
        }

        __syncthreads();                     // cmbuf zeroed by all before atomics

        // ---- epilogue: scalar STG (LD_ odd => no vector alignment) + maxima ----
        #pragma unroll
        for (int mi = 0; mi < 4; mi++) {
            int r0 = wm * 64 + mi * 16 + (lane >> 2);
            float m0 = -1e30f, m1 = -1e30f;
            #pragma unroll
            for (int ni = 0; ni < 4; ni++) {
                int col = wn * 32 + ni * 8 + (lane & 3) * 2;
                float c0 = acc[mi][ni][0] * INV_T, c1 = acc[mi][ni][1] * INV_T;
                float c2 = acc[mi][ni][2] * INV_T, c3 = acc[mi][ni][3] * INV_T;
                size_t gb = (size_t)(mt * 128 + r0) * LD_ + 1 + nb + col;
                out[gb]     = c0;
                out[gb + 1] = c1;
                out[gb + (size_t)8 * LD_]     = c2;
                out[gb + (size_t)8 * LD_ + 1] = c3;
                m0 = fmaxf(m0, fmaxf(c0, c1));
                m1 = fmaxf(m1, fmaxf(c2, c3));
            }
            // reduce over the 4 lanes sharing each row
            #pragma unroll
            for (int o = 1; o < 4; o <<= 1) {
                m0 = fmaxf(m0, __shfl_xor_sync(0xffffffffu, m0, o));
                m1 = fmaxf(m1, __shfl_xor_sync(0xffffffffu, m1, o));
            }
            if ((lane & 3) == 0) {
                int half = wn >> 1;
                atomicMax(&cmbuf[(r0) * 2 + half], fkey(m0));
                atomicMax(&cmbuf[(r0 + 8) * 2 + half], fkey(m1));
            }
        }
        __syncthreads();
        if (t < 256) {
            int row = t >> 1, half = t & 1;
            g_cmaxu[(size_t)(mt * 128 + row) * NC64 + ci * 2 + half] = cmbuf[t];
        }
        cur = nxt;
    }
}

// ---------------- k3: exact top-32 via exact 32nd chunk-max ----------------
// T = 32nd-largest chunk-max key. Then >=32 elements (the top-32 chunk maxima)
// are >= T, so 32nd-largest element >= T; every top-32 element >= that, and
// lives in a chunk whose max >= it >= T. Scan only chunks with key >= T.
#define CHCAP 512
#define CCAP  2048

__global__ void __launch_bounds__(512)
k3_topk(const float* __restrict__ out) {
    __shared__ unsigned keys[NC64];
    __shared__ int chl[CHCAP];
    __shared__ unsigned long long cand[CCAP];
    __shared__ unsigned s_T, s_nch, s_nc;
    int t = threadIdx.x, lane = t & 31, w = t >> 5;
    int r = blockIdx.x;
    const float* row = out + (size_t)r * LD_ + 1;

    for (int i = t; i < NC64; i += 512) keys[i] = g_cmaxu[(size_t)r * NC64 + i];
    if (t == 0) { s_T = 0xFFFFFFFFu; s_nch = 0; s_nc = 0; }
    __syncthreads();

    // exact 32nd-largest key (ties-safe: min key with strict-rank < 32)
    for (int i = t; i < NC64; i += 512) {
        unsigned ki = keys[i];
        int c = 0;
        for (int j = 0; j < NC64; j++) c += (keys[j] > ki) ? 1 : 0;
        if (c < 32) atomicMin(&s_T, ki);
    }
    __syncthreads();
    unsigned T = s_T;

    for (int i = t; i < NC64; i += 512)
        if (keys[i] >= T) {
            unsigned p = atomicAdd(&s_nch, 1u);
            if (p < CHCAP) chl[p] = i;
        }
    __syncthreads();

    if (s_nch <= CHCAP) {
        int nch = (int)s_nch;
        for (int cidx = w; cidx < nch; cidx += 16) {
            int cbase = chl[cidx] * 64;
            #pragma unroll
            for (int e = 0; e < 2; e++) {
                int j = cbase + lane * 2 + e;
                unsigned fk = fkey(row[j]);
                if (fk >= T) {
                    unsigned p = atomicAdd(&s_nc, 1u);
                    if (p < CCAP)
                        cand[p] = ((unsigned long long)fk << 32) | (unsigned)(~(unsigned)j);
                }
            }
        }
    } else {
        for (int j = t; j < KQ; j += 512) {
            unsigned fk = fkey(row[j]);
            if (fk >= T) {
                unsigned p = atomicAdd(&s_nc, 1u);
                if (p < CCAP)
                    cand[p] = ((unsigned long long)fk << 32) | (unsigned)(~(unsigned)j);
            }
        }
    }
    __syncthreads();
    int n = (int)min(s_nc, (unsigned)CCAP);

    // exact, order-independent rank-by-count (keys unique: value|~idx)
    for (int i = t; i < n; i += 512) {
        unsigned long long key = cand[i];
        int rank = 0;
        for (int j = 0; j < n; j++) rank += (cand[j] > key) ? 1 : 0;
        if (rank < 32) g_hard[r * 32 + rank] = (int)(~(unsigned)(key & 0xFFFFFFFFull));
    }
}

// ---------------- k4: mixed hard-negative logits ---------------------------
__global__ void k4_mix(const float* __restrict__ queue, const float* __restrict__ alpha,
                       const float* __restrict__ beta, const int* __restrict__ i1a,
                       const int* __restrict__ i1b, const int* __restrict__ i2,
                       float* __restrict__ out) {
    __shared__ float qsh[D_];
    __shared__ int hsh[32];
    int t = threadIdx.x, lane = t & 31, w = t >> 5;
    int r = blockIdx.x;
    if (t < D_) qsh[t] = g_outq[(size_t)r * D_ + t];
    if (t < 32) hsh[t] = g_hard[r * 32 + t];
    __syncthreads();
    float4 q4 = *(float4*)&qsh[lane * 4];

    #pragma unroll
    for (int e = 0; e < 2; e++) {
        int s = w * 2 + e;
        {
            int g1 = hsh[i1a[r * 16 + s]];
            int g2 = hsh[i1b[r * 16 + s]];
            float a = alpha[r * 16 + s];
            float4 n1 = *(const float4*)(queue + (size_t)g1 * D_ + lane * 4);
            float4 n2 = *(const float4*)(queue + (size_t)g2 * D_ + lane * 4);
            float4 v;
            v.x = a * n1.x + (1.f - a) * n2.x;
            v.y = a * n1.y + (1.f - a) * n2.y;
            v.z = a * n1.z + (1.f - a) * n2.z;
            v.w = a * n1.w + (1.f - a) * n2.w;
            float ss = v.x*v.x + v.y*v.y + v.z*v.z + v.w*v.w;
            float dq = v.x*q4.x + v.y*q4.y + v.z*q4.z + v.w*q4.w;
            #pragma unroll
            for (int o = 16; o; o >>= 1) {
                ss += __shfl_xor_sync(0xffffffffu, ss, o);
                dq += __shfl_xor_sync(0xffffffffu, dq, o);
            }
            if (lane == 0)
                out[(size_t)r * LD_ + 1 + KQ + s] = dq / fmaxf(sqrtf(ss), 1e-12f) * INV_T;
        }
        {
            int g = hsh[i2[r * 16 + s]];
            float bb = beta[r * 16 + s] * 0.5f;
            float4 n1 = *(const float4*)(queue + (size_t)g * D_ + lane * 4);
            float4 v;
            v.x = bb * q4.x + (1.f - bb) * n1.x;
            v.y = bb * q4.y + (1.f - bb) * n1.y;
            v.z = bb * q4.z + (1.f - bb) * n1.z;
            v.w = bb * q4.w + (1.f - bb) * n1.w;
            float ss = v.x*v.x + v.y*v.y + v.z*v.z + v.w*v.w;
            float dq = v.x*q4.x + v.y*q4.y + v.z*q4.z + v.w*q4.w;
            #pragma unroll
            for (int o = 16; o; o >>= 1) {
                ss += __shfl_xor_sync(0xffffffffu, ss, o);
                dq += __shfl_xor_sync(0xffffffffu, dq, o);
            }
            if (lane == 0)
                out[(size_t)r * LD_ + 1 + KQ + 16 + s] = dq / fmaxf(sqrtf(ss), 1e-12f) * INV_T;
        }
    }
}

// ---------------- tail: zero any region past logits ------------------------
__global__ void k_tail(float* __restrict__ out, int total) {
    for (int j = B_ * LD_ + blockIdx.x * blockDim.x + threadIdx.x; j < total;
         j += gridDim.x * blockDim.x)
        out[j] = 0.f;
}

// ---------------- launch ---------------------------------------------------
extern "C" void kernel_launch(void* const* d_in, const int* in_sizes, int n_in,
                              void* d_out, int out_size) {
    const float* q     = (const float*)d_in[0];
    const float* k     = (const float*)d_in[1];
    const float* Wq    = (const float*)d_in[2];
    const float* Wk    = (const float*)d_in[3];
    const float* queue = (const float*)d_in[4];
    const float* alpha = (const float*)d_in[5];
    const float* beta  = (const float*)d_in[6];
    const int*   i1a   = (const int*)d_in[7];
    const int*   i1b   = (const int*)d_in[8];
    const int*   i2    = (const int*)d_in[9];
    float* out = (float*)d_out;

    cudaFuncSetAttribute(k2p_gemm, cudaFuncAttributeMaxDynamicSharedMemorySize, K2P_SMEM);

    k1_gemm<<<dim3(16, SPLITK), 256>>>(q, k, Wq, Wk);        // launch 1
    k1b_norm<<<8, 256>>>(out);                                // launch 2
    k_pos3<<<1, 32>>>();                                      // launch 3 (spacer)
    k2p_gemm<<<dim3(CSTRIDE, 2), 256, K2P_SMEM>>>(queue, out); // launch 4 <- ncu
    k3_topk<<<256, 512>>>(out);                               // launch 5
    k4_mix<<<256, 256>>>(queue, alpha, beta, i1a, i1b, i2, out);
    if (out_size > B_ * LD_) k_tail<<<1, 256>>>(out, out_size);
}

// round 13
// speedup vs baseline: 1.2528x; 1.2528x over previous
#include <cuda_runtime.h>
#include <cuda_bf16.h>
#include <cstdint>
#include <cstring>

#define B_    256
#define IND   2048
#define D_    128
#define KQ    65536
#define LD_   65569              /* 1 + K + S1 + S2 */
#define INV_T (1.0f/0.07f)
#define SPLITK 8
#define NC64  1024               /* 64-wide chunks per row */

// ---------------- device scratch (no allocation allowed) -------------------
__device__ __align__(16) float g_pq[SPLITK * B_ * D_];
__device__ __align__(16) float g_pk[SPLITK * B_ * D_];
__device__ __align__(16) float g_outq[B_ * D_];          // normalized out_q
__device__ __align__(16) unsigned short g_ah[B_ * D_];   // bf16 hi of out_q
__device__ __align__(16) unsigned short g_al[B_ * D_];   // bf16 lo of out_q
__device__ __align__(16) unsigned g_cmaxu[B_ * NC64];    // fkey of per-64chunk max
__device__ int g_hard[B_ * 32];

__device__ __forceinline__ unsigned fkey(float f) {
    unsigned u = __float_as_uint(f);
    return (u >> 31) ? ~u : (u | 0x80000000u);
}
__device__ __forceinline__ uint32_t smem_u32(const void* p) {
    uint32_t a;
    asm("{ .reg .u64 t; cvta.to.shared.u64 t, %1; cvt.u32.u64 %0, t; }" : "=r"(a) : "l"(p));
    return a;
}
__device__ __forceinline__ void ldsm4(uint32_t* r, uint32_t a) {
    asm volatile("ldmatrix.sync.aligned.m8n8.x4.shared.b16 {%0,%1,%2,%3}, [%4];"
                 : "=r"(r[0]), "=r"(r[1]), "=r"(r[2]), "=r"(r[3]) : "r"(a));
}
__device__ __forceinline__ void mma16816(float* c, const uint32_t* a, uint32_t b0, uint32_t b1) {
    asm volatile(
        "mma.sync.aligned.m16n8k16.row.col.f32.bf16.bf16.f32 "
        "{%0,%1,%2,%3}, {%4,%5,%6,%7}, {%8,%9}, {%0,%1,%2,%3};"
        : "+f"(c[0]), "+f"(c[1]), "+f"(c[2]), "+f"(c[3])
        : "r"(a[0]), "r"(a[1]), "r"(a[2]), "r"(a[3]), "r"(b0), "r"(b1));
}

// ---------------- k1: encoder GEMMs, split-K=8 -----------------------------
__global__ void k1_gemm(const float* __restrict__ q, const float* __restrict__ kk,
                        const float* __restrict__ Wq, const float* __restrict__ Wk) {
    __shared__ float qs[16][32];
    __shared__ float ks[16][32];
    const float C0 = 0.999f, C1 = 1.0f - 0.999f;
    int t = threadIdx.x;
    int c = t & 127, h = t >> 7;
    int rb = blockIdx.x * 16;
    int k0 = blockIdx.y * (IND / SPLITK);

    float aq[8], ak[8];
    #pragma unroll
    for (int j = 0; j < 8; j++) { aq[j] = 0.f; ak[j] = 0.f; }

    for (int kc = 0; kc < IND / SPLITK; kc += 32) {
        __syncthreads();
        #pragma unroll
        for (int e = 0; e < 2; e++) {
            int id = t + e * 256;
            int r = id >> 5, i = id & 31;
            qs[r][i] = q [(size_t)(rb + r) * IND + k0 + kc + i];
            ks[r][i] = kk[(size_t)(rb + r) * IND + k0 + kc + i];
        }
        __syncthreads();
        #pragma unroll
        for (int u0 = 0; u0 < 32; u0 += 8) {
            float wq[8], wm[8];
            #pragma unroll
            for (int u = 0; u < 8; u++) {
                float a = Wq[(size_t)(k0 + kc + u0 + u) * D_ + c];
                float b = Wk[(size_t)(k0 + kc + u0 + u) * D_ + c];
                wq[u] = a;
                wm[u] = C0 * b + C1 * a;
            }
            #pragma unroll
            for (int u = 0; u < 8; u++)
                #pragma unroll
                for (int j = 0; j < 8; j++) {
                    aq[j] = fmaf(qs[h * 8 + j][u0 + u], wq[u], aq[j]);
                    ak[j] = fmaf(ks[h * 8 + j][u0 + u], wm[u], ak[j]);
                }
        }
    }
    int sk = blockIdx.y;
    #pragma unroll
    for (int j = 0; j < 8; j++) {
        int r = rb + h * 8 + j;
        g_pq[((size_t)sk * B_ + r) * D_ + c] = aq[j];
        g_pk[((size_t)sk * B_ + r) * D_ + c] = ak[j];
    }
}

// ---------------- k1b: reduce, normalize, pos logit, bf16 hi/lo split ------
__global__ void k1b_norm(float* __restrict__ out) {
    int t = threadIdx.x, lane = t & 31, w = t >> 5;
    int rb = blockIdx.x * 32;
    for (int rr = 0; rr < 4; rr++) {
        int r = rb + rr * 8 + w;
        float4 q4 = make_float4(0.f, 0.f, 0.f, 0.f);
        float4 k4 = make_float4(0.f, 0.f, 0.f, 0.f);
        #pragma unroll
        for (int s = 0; s < SPLITK; s++) {
            float4 a = *(const float4*)&g_pq[((size_t)s * B_ + r) * D_ + lane * 4];
            float4 b = *(const float4*)&g_pk[((size_t)s * B_ + r) * D_ + lane * 4];
            q4.x += a.x; q4.y += a.y; q4.z += a.z; q4.w += a.w;
            k4.x += b.x; k4.y += b.y; k4.z += b.z; k4.w += b.w;
        }
        float s1 = q4.x*q4.x + q4.y*q4.y + q4.z*q4.z + q4.w*q4.w;
        float s2 = k4.x*k4.x + k4.y*k4.y + k4.z*k4.z + k4.w*k4.w;
        float s3 = q4.x*k4.x + q4.y*k4.y + q4.z*k4.z + q4.w*k4.w;
        #pragma unroll
        for (int o = 16; o; o >>= 1) {
            s1 += __shfl_xor_sync(0xffffffffu, s1, o);
            s2 += __shfl_xor_sync(0xffffffffu, s2, o);
            s3 += __shfl_xor_sync(0xffffffffu, s3, o);
        }
        float invq = 1.f / fmaxf(sqrtf(s1), 1e-12f);
        float invk = 1.f / fmaxf(sqrtf(s2), 1e-12f);
        float vs[4] = {q4.x * invq, q4.y * invq, q4.z * invq, q4.w * invq};
        *(float4*)&g_outq[(size_t)r * D_ + lane * 4] = make_float4(vs[0], vs[1], vs[2], vs[3]);
        unsigned hs[4], ls[4];
        #pragma unroll
        for (int j = 0; j < 4; j++) {
            __nv_bfloat16 hb = __float2bfloat16_rn(vs[j]);
            float lo = vs[j] - __bfloat162float(hb);
            hs[j] = (unsigned)__bfloat16_as_ushort(hb);
            ls[j] = (unsigned)__bfloat16_as_ushort(__float2bfloat16_rn(lo));
        }
        ((uint2*)g_ah)[r * 32 + lane] = make_uint2(hs[0] | (hs[1] << 16), hs[2] | (hs[3] << 16));
        ((uint2*)g_al)[r * 32 + lane] = make_uint2(ls[0] | (ls[1] << 16), ls[2] | (ls[3] << 16));
        if (lane == 0) out[(size_t)r * LD_] = s3 * invq * invk * INV_T;
    }
}

// ---------------- k2m: HMMA bf16 3-term GEMM (R10-proven, 94.5us) ----------
// grid (1024 N-chunks of 64, 2 M-tiles of 128). Block 256 thr = 8 warps,
// warp grid 4(M)x2(N), warp tile 32x32, mma.sync.m16n8k16.
// smem XOR-swizzled (16B chunk ^ (row&7)) -> conflict-free ldmatrix.
#define AH_O 0
#define AL_O 32768
#define BH_O 65536
#define BL_O (65536 + 16384)
#define K2M_SMEM (65536 + 32768)      /* 96 KB */
#define STG_W 66

__global__ void __launch_bounds__(256, 2)
k2m_gemm(const float* __restrict__ queue, float* __restrict__ out) {
    extern __shared__ __align__(16) char smc[];
    int t = threadIdx.x, lane = t & 31, w = t >> 5;
    int wm = w & 3, wn = w >> 2;
    int ci = blockIdx.x, mt = blockIdx.y;
    int nb = ci * 64;

    // ---- load A halves (bf16 in gmem) into swizzled smem ----
    #pragma unroll
    for (int it = 0; it < 8; it++) {
        int cid = t + it * 256;                 // 2048 16B chunks
        int r = cid >> 4, c = cid & 15;
        uint32_t dst = (uint32_t)(r * 256 + ((c ^ (r & 7)) << 4));
        int gi = (mt * 128 + r) * 16 + c;
        *(uint4*)(smc + AH_O + dst) = ((const uint4*)g_ah)[gi];
        *(uint4*)(smc + AL_O + dst) = ((const uint4*)g_al)[gi];
    }
    // ---- load B tile (queue fp32 -> bf16 hi/lo) ----
    #pragma unroll
    for (int it = 0; it < 8; it++) {
        int cid = t + it * 256;                 // 2048 float4s (64 x 32)
        int n = cid >> 5, c4 = cid & 31;
        float4 v = *(const float4*)(queue + (size_t)(nb + n) * D_ + c4 * 4);
        float vv[4] = {v.x, v.y, v.z, v.w};
        unsigned hp[4], lp[4];
        #pragma unroll
        for (int j = 0; j < 4; j++) {
            __nv_bfloat16 hb = __float2bfloat16_rn(vv[j]);
            float lo = vv[j] - __bfloat162float(hb);
            hp[j] = (unsigned)__bfloat16_as_ushort(hb);
            lp[j] = (unsigned)__bfloat16_as_ushort(__float2bfloat16_rn(lo));
        }
        int c = c4 >> 1;
        uint32_t dst = (uint32_t)(n * 256 + ((c ^ (n & 7)) << 4) + (c4 & 1) * 8);
        *(uint2*)(smc + BH_O + dst) = make_uint2(hp[0] | (hp[1] << 16), hp[2] | (hp[3] << 16));
        *(uint2*)(smc + BL_O + dst) = make_uint2(lp[0] | (lp[1] << 16), lp[2] | (lp[3] << 16));
    }
    __syncthreads();

    uint32_t ah = smem_u32(smc + AH_O), al = smem_u32(smc + AL_O);
    uint32_t bh = smem_u32(smc + BH_O), bl = smem_u32(smc + BL_O);

    float acc[2][4][4];
    #pragma unroll
    for (int mi = 0; mi < 2; mi++)
        #pragma unroll
        for (int ni = 0; ni < 4; ni++)
            #pragma unroll
            for (int j = 0; j < 4; j++) acc[mi][ni][j] = 0.f;

    int l15 = lane & 15, sx = lane & 7, khalf = lane >> 4;

    #pragma unroll
    for (int ks = 0; ks < 8; ks++) {
        int kc = ks * 2 + khalf;
        uint32_t Ah[2][4], Al[2][4], Bh[2][4], Bl[2][4];
        #pragma unroll
        for (int mi = 0; mi < 2; mi++) {
            uint32_t off = (uint32_t)((wm * 32 + mi * 16 + l15) * 256 + ((kc ^ sx) << 4));
            ldsm4(Ah[mi], ah + off);
            ldsm4(Al[mi], al + off);
        }
        #pragma unroll
        for (int bi = 0; bi < 2; bi++) {
            uint32_t off = (uint32_t)((wn * 32 + bi * 16 + l15) * 256 + ((kc ^ sx) << 4));
            ldsm4(Bh[bi], bh + off);
            ldsm4(Bl[bi], bl + off);
        }
        #pragma unroll
        for (int mi = 0; mi < 2; mi++)
            #pragma unroll
            for (int ni = 0; ni < 4; ni++) {
                int bi = ni >> 1, j = ni & 1;
                mma16816(acc[mi][ni], Ah[mi], Bh[bi][j], Bh[bi][j + 2]);
                mma16816(acc[mi][ni], Ah[mi], Bl[bi][j], Bl[bi][j + 2]);
                mma16816(acc[mi][ni], Al[mi], Bh[bi][j], Bh[bi][j + 2]);
            }
    }
    __syncthreads();                            // done reading A/B smem

    // ---- stage fragments (stride-66), then coalesced stores + cmax ----
    float* stage = (float*)smc;
    #pragma unroll
    for (int mi = 0; mi < 2; mi++)
        #pragma unroll
        for (int ni = 0; ni < 4; ni++) {
            int row = wm * 32 + mi * 16 + (lane >> 2);
            int col = wn * 32 + ni * 8 + (lane & 3) * 2;
            *(float2*)&stage[row * STG_W + col] =
                make_float2(acc[mi][ni][0] * INV_T, acc[mi][ni][1] * INV_T);
            *(float2*)&stage[(row + 8) * STG_W + col] =
                make_float2(acc[mi][ni][2] * INV_T, acc[mi][ni][3] * INV_T);
        }
    __syncthreads();

    #pragma unroll 2
    for (int rr = 0; rr < 16; rr++) {
        int row = w * 16 + rr;
        float v0 = stage[row * STG_W + lane];
        float v1 = stage[row * STG_W + 32 + lane];
        size_t gb = (size_t)(mt * 128 + row) * LD_ + 1 + nb;
        out[gb + lane]      = v0;
        out[gb + 32 + lane] = v1;
        float m0 = fmaxf(v0, v1);
        #pragma unroll
        for (int o = 16; o; o >>= 1)
            m0 = fmaxf(m0, __shfl_xor_sync(0xffffffffu, m0, o));
        if (lane == 0)
            g_cmaxu[(size_t)(mt * 128 + row) * NC64 + ci] = fkey(m0);
    }
}

// ---------------- k3: exact top-32 via exact 32nd chunk-max ----------------
// (4th launch -> ncu capture slot this round)
#define CHCAP 512
#define CCAP  2048

__global__ void __launch_bounds__(512)
k3_topk(const float* __restrict__ out) {
    __shared__ unsigned keys[NC64];
    __shared__ int chl[CHCAP];
    __shared__ unsigned long long cand[CCAP];
    __shared__ unsigned s_T, s_nch, s_nc;
    int t = threadIdx.x, lane = t & 31, w = t >> 5;
    int r = blockIdx.x;
    const float* row = out + (size_t)r * LD_ + 1;

    for (int i = t; i < NC64; i += 512) keys[i] = g_cmaxu[(size_t)r * NC64 + i];
    if (t == 0) { s_T = 0xFFFFFFFFu; s_nch = 0; s_nc = 0; }
    __syncthreads();

    // exact 32nd-largest key (min key with strict-rank < 32)
    for (int i = t; i < NC64; i += 512) {
        unsigned ki = keys[i];
        int c = 0;
        for (int j = 0; j < NC64; j++) c += (keys[j] > ki) ? 1 : 0;
        if (c < 32) atomicMin(&s_T, ki);
    }
    __syncthreads();
    unsigned T = s_T;

    for (int i = t; i < NC64; i += 512)
        if (keys[i] >= T) {
            unsigned p = atomicAdd(&s_nch, 1u);
            if (p < CHCAP) chl[p] = i;
        }
    __syncthreads();

    if (s_nch <= CHCAP) {
        int nch = (int)s_nch;
        for (int cidx = w; cidx < nch; cidx += 16) {
            int cbase = chl[cidx] * 64;
            #pragma unroll
            for (int e = 0; e < 2; e++) {
                int j = cbase + lane * 2 + e;
                unsigned fk = fkey(row[j]);
                if (fk >= T) {
                    unsigned p = atomicAdd(&s_nc, 1u);
                    if (p < CCAP)
                        cand[p] = ((unsigned long long)fk << 32) | (unsigned)(~(unsigned)j);
                }
            }
        }
    } else {
        for (int j = t; j < KQ; j += 512) {
            unsigned fk = fkey(row[j]);
            if (fk >= T) {
                unsigned p = atomicAdd(&s_nc, 1u);
                if (p < CCAP)
                    cand[p] = ((unsigned long long)fk << 32) | (unsigned)(~(unsigned)j);
            }
        }
    }
    __syncthreads();
    int n = (int)min(s_nc, (unsigned)CCAP);

    // exact, order-independent rank-by-count (keys unique: value|~idx)
    for (int i = t; i < n; i += 512) {
        unsigned long long key = cand[i];
        int rank = 0;
        for (int j = 0; j < n; j++) rank += (cand[j] > key) ? 1 : 0;
        if (rank < 32) g_hard[r * 32 + rank] = (int)(~(unsigned)(key & 0xFFFFFFFFull));
    }
}

// ---------------- k4: mixed hard-negative logits ---------------------------
__global__ void k4_mix(const float* __restrict__ queue, const float* __restrict__ alpha,
                       const float* __restrict__ beta, const int* __restrict__ i1a,
                       const int* __restrict__ i1b, const int* __restrict__ i2,
                       float* __restrict__ out) {
    __shared__ float qsh[D_];
    __shared__ int hsh[32];
    int t = threadIdx.x, lane = t & 31, w = t >> 5;
    int r = blockIdx.x;
    if (t < D_) qsh[t] = g_outq[(size_t)r * D_ + t];
    if (t < 32) hsh[t] = g_hard[r * 32 + t];
    __syncthreads();
    float4 q4 = *(float4*)&qsh[lane * 4];

    #pragma unroll
    for (int e = 0; e < 2; e++) {
        int s = w * 2 + e;
        {
            int g1 = hsh[i1a[r * 16 + s]];
            int g2 = hsh[i1b[r * 16 + s]];
            float a = alpha[r * 16 + s];
            float4 n1 = *(const float4*)(queue + (size_t)g1 * D_ + lane * 4);
            float4 n2 = *(const float4*)(queue + (size_t)g2 * D_ + lane * 4);
            float4 v;
            v.x = a * n1.x + (1.f - a) * n2.x;
            v.y = a * n1.y + (1.f - a) * n2.y;
            v.z = a * n1.z + (1.f - a) * n2.z;
            v.w = a * n1.w + (1.f - a) * n2.w;
            float ss = v.x*v.x + v.y*v.y + v.z*v.z + v.w*v.w;
            float dq = v.x*q4.x + v.y*q4.y + v.z*q4.z + v.w*q4.w;
            #pragma unroll
            for (int o = 16; o; o >>= 1) {
                ss += __shfl_xor_sync(0xffffffffu, ss, o);
                dq += __shfl_xor_sync(0xffffffffu, dq, o);
            }
            if (lane == 0)
                out[(size_t)r * LD_ + 1 + KQ + s] = dq / fmaxf(sqrtf(ss), 1e-12f) * INV_T;
        }
        {
            int g = hsh[i2[r * 16 + s]];
            float bb = beta[r * 16 + s] * 0.5f;
            float4 n1 = *(const float4*)(queue + (size_t)g * D_ + lane * 4);
            float4 v;
            v.x = bb * q4.x + (1.f - bb) * n1.x;
            v.y = bb * q4.y + (1.f - bb) * n1.y;
            v.z = bb * q4.z + (1.f - bb) * n1.z;
            v.w = bb * q4.w + (1.f - bb) * n1.w;
            float ss = v.x*v.x + v.y*v.y + v.z*v.z + v.w*v.w;
            float dq = v.x*q4.x + v.y*q4.y + v.z*q4.z + v.w*q4.w;
            #pragma unroll
            for (int o = 16; o; o >>= 1) {
                ss += __shfl_xor_sync(0xffffffffu, ss, o);
                dq += __shfl_xor_sync(0xffffffffu, dq, o);
            }
            if (lane == 0)
                out[(size_t)r * LD_ + 1 + KQ + 16 + s] = dq / fmaxf(sqrtf(ss), 1e-12f) * INV_T;
        }
    }
}

// ---------------- tail: zero any region past logits ------------------------
__global__ void k_tail(float* __restrict__ out, int total) {
    for (int j = B_ * LD_ + blockIdx.x * blockDim.x + threadIdx.x; j < total;
         j += gridDim.x * blockDim.x)
        out[j] = 0.f;
}

// ---------------- launch ---------------------------------------------------
extern "C" void kernel_launch(void* const* d_in, const int* in_sizes, int n_in,
                              void* d_out, int out_size) {
    const float* q     = (const float*)d_in[0];
    const float* k     = (const float*)d_in[1];
    const float* Wq    = (const float*)d_in[2];
    const float* Wk    = (const float*)d_in[3];
    const float* queue = (const float*)d_in[4];
    const float* alpha = (const float*)d_in[5];
    const float* beta  = (const float*)d_in[6];
    const int*   i1a   = (const int*)d_in[7];
    const int*   i1b   = (const int*)d_in[8];
    const int*   i2    = (const int*)d_in[9];
    float* out = (float*)d_out;

    cudaFuncSetAttribute(k2m_gemm, cudaFuncAttributeMaxDynamicSharedMemorySize, K2M_SMEM);

    k1_gemm<<<dim3(16, SPLITK), 256>>>(q, k, Wq, Wk);        // launch 1
    k1b_norm<<<8, 256>>>(out);                                // launch 2
    k2m_gemm<<<dim3(1024, 2), 256, K2M_SMEM>>>(queue, out);   // launch 3
    k3_topk<<<256, 512>>>(out);                               // launch 4 <- ncu
    k4_mix<<<256, 256>>>(queue, alpha, beta, i1a, i1b, i2, out);
    if (out_size > B_ * LD_) k_tail<<<1, 256>>>(out, out_size);
}

// round 15
// speedup vs baseline: 1.3874x; 1.1074x over previous
#include <cuda_runtime.h>
#include <cuda_bf16.h>
#include <cstdint>
#include <cstring>

#define B_    256
#define IND   2048
#define D_    128
#define KQ    65536
#define LD_   65569              /* 1 + K + S1 + S2 */
#define INV_T (1.0f/0.07f)
#define SPLITK 8
#define NC64  1024               /* 64-wide chunks per row */

// ---------------- device scratch (no allocation allowed) -------------------
__device__ __align__(16) float g_pq[SPLITK * B_ * D_];
__device__ __align__(16) float g_pk[SPLITK * B_ * D_];
__device__ __align__(16) float g_outq[B_ * D_];          // normalized out_q
__device__ __align__(16) unsigned short g_ah[B_ * D_];   // bf16 hi of out_q
__device__ __align__(16) unsigned short g_al[B_ * D_];   // bf16 lo of out_q
__device__ __align__(16) unsigned g_cmaxu[B_ * NC64];    // fkey of per-64chunk max
__device__ int g_hard[B_ * 32];

__device__ __forceinline__ unsigned fkey(float f) {
    unsigned u = __float_as_uint(f);
    return (u >> 31) ? ~u : (u | 0x80000000u);
}
__device__ __forceinline__ uint32_t smem_u32(const void* p) {
    uint32_t a;
    asm("{ .reg .u64 t; cvta.to.shared.u64 t, %1; cvt.u32.u64 %0, t; }" : "=r"(a) : "l"(p));
    return a;
}
__device__ __forceinline__ void ldsm4(uint32_t* r, uint32_t a) {
    asm volatile("ldmatrix.sync.aligned.m8n8.x4.shared.b16 {%0,%1,%2,%3}, [%4];"
                 : "=r"(r[0]), "=r"(r[1]), "=r"(r[2]), "=r"(r[3]) : "r"(a));
}
__device__ __forceinline__ void mma16816(float* c, const uint32_t* a, uint32_t b0, uint32_t b1) {
    asm volatile(
        "mma.sync.aligned.m16n8k16.row.col.f32.bf16.bf16.f32 "
        "{%0,%1,%2,%3}, {%4,%5,%6,%7}, {%8,%9}, {%0,%1,%2,%3};"
        : "+f"(c[0]), "+f"(c[1]), "+f"(c[2]), "+f"(c[3])
        : "r"(a[0]), "r"(a[1]), "r"(a[2]), "r"(a[3]), "r"(b0), "r"(b1));
}

// ---------------- k1: encoder GEMMs, split-K=8, LDS.128 reads --------------
__global__ void k1_gemm(const float* __restrict__ q, const float* __restrict__ kk,
                        const float* __restrict__ Wq, const float* __restrict__ Wk) {
    __shared__ __align__(16) float qs[16][32];
    __shared__ __align__(16) float ks[16][32];
    const float C0 = 0.999f, C1 = 1.0f - 0.999f;
    int t = threadIdx.x;
    int c = t & 127, h = t >> 7;
    int rb = blockIdx.x * 16;
    int k0 = blockIdx.y * (IND / SPLITK);

    float aq[8], ak[8];
    #pragma unroll
    for (int j = 0; j < 8; j++) { aq[j] = 0.f; ak[j] = 0.f; }

    for (int kc = 0; kc < IND / SPLITK; kc += 32) {
        __syncthreads();
        #pragma unroll
        for (int e = 0; e < 2; e++) {
            int id = t + e * 256;
            int r = id >> 5, i = id & 31;
            qs[r][i] = q [(size_t)(rb + r) * IND + k0 + kc + i];
            ks[r][i] = kk[(size_t)(rb + r) * IND + k0 + kc + i];
        }
        __syncthreads();
        #pragma unroll
        for (int u0 = 0; u0 < 32; u0 += 4) {
            float wq[4], wm[4];
            #pragma unroll
            for (int u = 0; u < 4; u++) {
                float a = Wq[(size_t)(k0 + kc + u0 + u) * D_ + c];
                float b = Wk[(size_t)(k0 + kc + u0 + u) * D_ + c];
                wq[u] = a;
                wm[u] = C0 * b + C1 * a;
            }
            #pragma unroll
            for (int j = 0; j < 8; j++) {
                float4 qv = *(const float4*)&qs[h * 8 + j][u0];
                float4 kv = *(const float4*)&ks[h * 8 + j][u0];
                aq[j] = fmaf(qv.x, wq[0], fmaf(qv.y, wq[1], fmaf(qv.z, wq[2], fmaf(qv.w, wq[3], aq[j]))));
                ak[j] = fmaf(kv.x, wm[0], fmaf(kv.y, wm[1], fmaf(kv.z, wm[2], fmaf(kv.w, wm[3], ak[j]))));
            }
        }
    }
    int sk = blockIdx.y;
    #pragma unroll
    for (int j = 0; j < 8; j++) {
        int r = rb + h * 8 + j;
        g_pq[((size_t)sk * B_ + r) * D_ + c] = aq[j];
        g_pk[((size_t)sk * B_ + r) * D_ + c] = ak[j];
    }
}

// ---------------- k1b: reduce, normalize, pos logit, bf16 hi/lo split ------
__global__ void k1b_norm(float* __restrict__ out) {
    int t = threadIdx.x, lane = t & 31, w = t >> 5;
    int rb = blockIdx.x * 32;
    for (int rr = 0; rr < 4; rr++) {
        int r = rb + rr * 8 + w;
        float4 q4 = make_float4(0.f, 0.f, 0.f, 0.f);
        float4 k4 = make_float4(0.f, 0.f, 0.f, 0.f);
        #pragma unroll
        for (int s = 0; s < SPLITK; s++) {
            float4 a = *(const float4*)&g_pq[((size_t)s * B_ + r) * D_ + lane * 4];
            float4 b = *(const float4*)&g_pk[((size_t)s * B_ + r) * D_ + lane * 4];
            q4.x += a.x; q4.y += a.y; q4.z += a.z; q4.w += a.w;
            k4.x += b.x; k4.y += b.y; k4.z += b.z; k4.w += b.w;
        }
        float s1 = q4.x*q4.x + q4.y*q4.y + q4.z*q4.z + q4.w*q4.w;
        float s2 = k4.x*k4.x + k4.y*k4.y + k4.z*k4.z + k4.w*k4.w;
        float s3 = q4.x*k4.x + q4.y*k4.y + q4.z*k4.z + q4.w*k4.w;
        #pragma unroll
        for (int o = 16; o; o >>= 1) {
            s1 += __shfl_xor_sync(0xffffffffu, s1, o);
            s2 += __shfl_xor_sync(0xffffffffu, s2, o);
            s3 += __shfl_xor_sync(0xffffffffu, s3, o);
        }
        float invq = 1.f / fmaxf(sqrtf(s1), 1e-12f);
        float invk = 1.f / fmaxf(sqrtf(s2), 1e-12f);
        float vs[4] = {q4.x * invq, q4.y * invq, q4.z * invq, q4.w * invq};
        *(float4*)&g_outq[(size_t)r * D_ + lane * 4] = make_float4(vs[0], vs[1], vs[2], vs[3]);
        unsigned hs[4], ls[4];
        #pragma unroll
        for (int j = 0; j < 4; j++) {
            __nv_bfloat16 hb = __float2bfloat16_rn(vs[j]);
            float lo = vs[j] - __bfloat162float(hb);
            hs[j] = (unsigned)__bfloat16_as_ushort(hb);
            ls[j] = (unsigned)__bfloat16_as_ushort(__float2bfloat16_rn(lo));
        }
        ((uint2*)g_ah)[r * 32 + lane] = make_uint2(hs[0] | (hs[1] << 16), hs[2] | (hs[3] << 16));
        ((uint2*)g_al)[r * 32 + lane] = make_uint2(ls[0] | (ls[1] << 16), ls[2] | (ls[3] << 16));
        if (lane == 0) out[(size_t)r * LD_] = s3 * invq * invk * INV_T;
    }
}

// ---------------- k2m: HMMA bf16 3-term GEMM (R10-proven, 94.5us) ----------
#define AH_O 0
#define AL_O 32768
#define BH_O 65536
#define BL_O (65536 + 16384)
#define K2M_SMEM (65536 + 32768)      /* 96 KB */
#define STG_W 66

__global__ void __launch_bounds__(256, 2)
k2m_gemm(const float* __restrict__ queue, float* __restrict__ out) {
    extern __shared__ __align__(16) char smc[];
    int t = threadIdx.x, lane = t & 31, w = t >> 5;
    int wm = w & 3, wn = w >> 2;
    int ci = blockIdx.x, mt = blockIdx.y;
    int nb = ci * 64;

    #pragma unroll
    for (int it = 0; it < 8; it++) {
        int cid = t + it * 256;
        int r = cid >> 4, c = cid & 15;
        uint32_t dst = (uint32_t)(r * 256 + ((c ^ (r & 7)) << 4));
        int gi = (mt * 128 + r) * 16 + c;
        *(uint4*)(smc + AH_O + dst) = ((const uint4*)g_ah)[gi];
        *(uint4*)(smc + AL_O + dst) = ((const uint4*)g_al)[gi];
    }
    #pragma unroll
    for (int it = 0; it < 8; it++) {
        int cid = t + it * 256;
        int n = cid >> 5, c4 = cid & 31;
        float4 v = *(const float4*)(queue + (size_t)(nb + n) * D_ + c4 * 4);
        float vv[4] = {v.x, v.y, v.z, v.w};
        unsigned hp[4], lp[4];
        #pragma unroll
        for (int j = 0; j < 4; j++) {
            __nv_bfloat16 hb = __float2bfloat16_rn(vv[j]);
            float lo = vv[j] - __bfloat162float(hb);
            hp[j] = (unsigned)__bfloat16_as_ushort(hb);
            lp[j] = (unsigned)__bfloat16_as_ushort(__float2bfloat16_rn(lo));
        }
        int c = c4 >> 1;
        uint32_t dst = (uint32_t)(n * 256 + ((c ^ (n & 7)) << 4) + (c4 & 1) * 8);
        *(uint2*)(smc + BH_O + dst) = make_uint2(hp[0] | (hp[1] << 16), hp[2] | (hp[3] << 16));
        *(uint2*)(smc + BL_O + dst) = make_uint2(lp[0] | (lp[1] << 16), lp[2] | (lp[3] << 16));
    }
    __syncthreads();

    uint32_t ah = smem_u32(smc + AH_O), al = smem_u32(smc + AL_O);
    uint32_t bh = smem_u32(smc + BH_O), bl = smem_u32(smc + BL_O);

    float acc[2][4][4];
    #pragma unroll
    for (int mi = 0; mi < 2; mi++)
        #pragma unroll
        for (int ni = 0; ni < 4; ni++)
            #pragma unroll
            for (int j = 0; j < 4; j++) acc[mi][ni][j] = 0.f;

    int l15 = lane & 15, sx = lane & 7, khalf = lane >> 4;

    #pragma unroll
    for (int ks = 0; ks < 8; ks++) {
        int kc = ks * 2 + khalf;
        uint32_t Ah[2][4], Al[2][4], Bh[2][4], Bl[2][4];
        #pragma unroll
        for (int mi = 0; mi < 2; mi++) {
            uint32_t off = (uint32_t)((wm * 32 + mi * 16 + l15) * 256 + ((kc ^ sx) << 4));
            ldsm4(Ah[mi], ah + off);
            ldsm4(Al[mi], al + off);
        }
        #pragma unroll
        for (int bi = 0; bi < 2; bi++) {
            uint32_t off = (uint32_t)((wn * 32 + bi * 16 + l15) * 256 + ((kc ^ sx) << 4));
            ldsm4(Bh[bi], bh + off);
            ldsm4(Bl[bi], bl + off);
        }
        #pragma unroll
        for (int mi = 0; mi < 2; mi++)
            #pragma unroll
            for (int ni = 0; ni < 4; ni++) {
                int bi = ni >> 1, j = ni & 1;
                mma16816(acc[mi][ni], Ah[mi], Bh[bi][j], Bh[bi][j + 2]);
                mma16816(acc[mi][ni], Ah[mi], Bl[bi][j], Bl[bi][j + 2]);
                mma16816(acc[mi][ni], Al[mi], Bh[bi][j], Bh[bi][j + 2]);
            }
    }
    __syncthreads();

    float* stage = (float*)smc;
    #pragma unroll
    for (int mi = 0; mi < 2; mi++)
        #pragma unroll
        for (int ni = 0; ni < 4; ni++) {
            int row = wm * 32 + mi * 16 + (lane >> 2);
            int col = wn * 32 + ni * 8 + (lane & 3) * 2;
            *(float2*)&stage[row * STG_W + col] =
                make_float2(acc[mi][ni][0] * INV_T, acc[mi][ni][1] * INV_T);
            *(float2*)&stage[(row + 8) * STG_W + col] =
                make_float2(acc[mi][ni][2] * INV_T, acc[mi][ni][3] * INV_T);
        }
    __syncthreads();

    #pragma unroll 2
    for (int rr = 0; rr < 16; rr++) {
        int row = w * 16 + rr;
        float v0 = stage[row * STG_W + lane];
        float v1 = stage[row * STG_W + 32 + lane];
        size_t gb = (size_t)(mt * 128 + row) * LD_ + 1 + nb;
        out[gb + lane]      = v0;
        out[gb + 32 + lane] = v1;
        float m0 = fmaxf(v0, v1);
        #pragma unroll
        for (int o = 16; o; o >>= 1)
            m0 = fmaxf(m0, __shfl_xor_sync(0xffffffffu, m0, o));
        if (lane == 0)
            g_cmaxu[(size_t)(mt * 128 + row) * NC64 + ci] = fkey(m0);
    }
}

// ---------------- k3: exact top-32, radix-select threshold -----------------
// T = exact 32nd-largest chunk-max key via 32-bit MSB-first binary search
// (max v with count(keys >= v) >= 32). Then: 32nd-largest ELEMENT >= T, and
// every top-32 element lives in a chunk with cmax >= T -> scan only those.
#define CHCAP 512
#define CCAP  2048

__global__ void __launch_bounds__(512)
k3_topk(const float* __restrict__ out) {
    __shared__ unsigned bitcnt[32];
    __shared__ int chl[CHCAP];
    __shared__ unsigned long long cand[CCAP];
    __shared__ unsigned s_nch, s_nc;
    int t = threadIdx.x, lane = t & 31, w = t >> 5;
    int r = blockIdx.x;
    const float* row = out + (size_t)r * LD_ + 1;

    unsigned ka = g_cmaxu[(size_t)r * NC64 + t];
    unsigned kb = g_cmaxu[(size_t)r * NC64 + 512 + t];
    if (t < 32) bitcnt[t] = 0;
    if (t == 0) { s_nch = 0; s_nc = 0; }
    __syncthreads();

    unsigned prefix = 0;
    #pragma unroll 1
    for (int b = 31; b >= 0; b--) {
        unsigned cv = prefix | (1u << b);
        int c = (int)(ka >= cv) + (int)(kb >= cv);
        #pragma unroll
        for (int o = 16; o; o >>= 1) c += __shfl_xor_sync(0xffffffffu, c, o);
        if (lane == 0 && c) atomicAdd(&bitcnt[b], (unsigned)c);
        __syncthreads();
        if (bitcnt[b] >= 32u) prefix = cv;
    }
    unsigned T = prefix;

    if (ka >= T) {
        unsigned p = atomicAdd(&s_nch, 1u);
        if (p < CHCAP) chl[p] = t;
    }
    if (kb >= T) {
        unsigned p = atomicAdd(&s_nch, 1u);
        if (p < CHCAP) chl[p] = 512 + t;
    }
    __syncthreads();

    if (s_nch <= CHCAP) {
        int nch = (int)s_nch;
        for (int cidx = w; cidx < nch; cidx += 16) {
            int cbase = chl[cidx] * 64;
            #pragma unroll
            for (int e = 0; e < 2; e++) {
                int j = cbase + lane * 2 + e;
                unsigned fk = fkey(row[j]);
                if (fk >= T) {
                    unsigned p = atomicAdd(&s_nc, 1u);
                    if (p < CCAP)
                        cand[p] = ((unsigned long long)fk << 32) | (unsigned)(~(unsigned)j);
                }
            }
        }
    } else {
        for (int j = t; j < KQ; j += 512) {
            unsigned fk = fkey(row[j]);
            if (fk >= T) {
                unsigned p = atomicAdd(&s_nc, 1u);
                if (p < CCAP)
                    cand[p] = ((unsigned long long)fk << 32) | (unsigned)(~(unsigned)j);
            }
        }
    }
    __syncthreads();
    int n = (int)min(s_nc, (unsigned)CCAP);

    // exact, order-independent rank-by-count over the (small) candidate set
    for (int i = t; i < n; i += 512) {
        unsigned long long key = cand[i];
        int rank = 0;
        for (int j = 0; j < n; j++) rank += (cand[j] > key) ? 1 : 0;
        if (rank < 32) g_hard[r * 32 + rank] = (int)(~(unsigned)(key & 0xFFFFFFFFull));
    }
}

// ---------------- k4: mixed hard-negative logits ---------------------------
__global__ void k4_mix(const float* __restrict__ queue, const float* __restrict__ alpha,
                       const float* __restrict__ beta, const int* __restrict__ i1a,
                       const int* __restrict__ i1b, const int* __restrict__ i2,
                       float* __restrict__ out) {
    __shared__ float qsh[D_];
    __shared__ int hsh[32];
    int t = threadIdx.x, lane = t & 31, w = t >> 5;
    int r = blockIdx.x;
    if (t < D_) qsh[t] = g_outq[(size_t)r * D_ + t];
    if (t < 32) hsh[t] = g_hard[r * 32 + t];
    __syncthreads();
    float4 q4 = *(float4*)&qsh[lane * 4];

    #pragma unroll
    for (int e = 0; e < 2; e++) {
        int s = w * 2 + e;
        {
            int g1 = hsh[i1a[r * 16 + s]];
            int g2 = hsh[i1b[r * 16 + s]];
            float a = alpha[r * 16 + s];
            float4 n1 = *(const float4*)(queue + (size_t)g1 * D_ + lane * 4);
            float4 n2 = *(const float4*)(queue + (size_t)g2 * D_ + lane * 4);
            float4 v;
            v.x = a * n1.x + (1.f - a) * n2.x;
            v.y = a * n1.y + (1.f - a) * n2.y;
            v.z = a * n1.z + (1.f - a) * n2.z;
            v.w = a * n1.w + (1.f - a) * n2.w;
            float ss = v.x*v.x + v.y*v.y + v.z*v.z + v.w*v.w;
            float dq = v.x*q4.x + v.y*q4.y + v.z*q4.z + v.w*q4.w;
            #pragma unroll
            for (int o = 16; o; o >>= 1) {
                ss += __shfl_xor_sync(0xffffffffu, ss, o);
                dq += __shfl_xor_sync(0xffffffffu, dq, o);
            }
            if (lane == 0)
                out[(size_t)r * LD_ + 1 + KQ + s] = dq / fmaxf(sqrtf(ss), 1e-12f) * INV_T;
        }
        {
            int g = hsh[i2[r * 16 + s]];
            float bb = beta[r * 16 + s] * 0.5f;
            float4 n1 = *(const float4*)(queue + (size_t)g * D_ + lane * 4);
            float4 v;
            v.x = bb * q4.x + (1.f - bb) * n1.x;
            v.y = bb * q4.y + (1.f - bb) * n1.y;
            v.z = bb * q4.z + (1.f - bb) * n1.z;
            v.w = bb * q4.w + (1.f - bb) * n1.w;
            float ss = v.x*v.x + v.y*v.y + v.z*v.z + v.w*v.w;
            float dq = v.x*q4.x + v.y*q4.y + v.z*q4.z + v.w*q4.w;
            #pragma unroll
            for (int o = 16; o; o >>= 1) {
                ss += __shfl_xor_sync(0xffffffffu, ss, o);
                dq += __shfl_xor_sync(0xffffffffu, dq, o);
            }
            if (lane == 0)
                out[(size_t)r * LD_ + 1 + KQ + 16 + s] = dq / fmaxf(sqrtf(ss), 1e-12f) * INV_T;
        }
    }
}

// ---------------- tail: zero any region past logits ------------------------
__global__ void k_tail(float* __restrict__ out, int total) {
    for (int j = B_ * LD_ + blockIdx.x * blockDim.x + threadIdx.x; j < total;
         j += gridDim.x * blockDim.x)
        out[j] = 0.f;
}

// ---------------- launch ---------------------------------------------------
extern "C" void kernel_launch(void* const* d_in, const int* in_sizes, int n_in,
                              void* d_out, int out_size) {
    const float* q     = (const float*)d_in[0];
    const float* k     = (const float*)d_in[1];
    const float* Wq    = (const float*)d_in[2];
    const float* Wk    = (const float*)d_in[3];
    const float* queue = (const float*)d_in[4];
    const float* alpha = (const float*)d_in[5];
    const float* beta  = (const float*)d_in[6];
    const int*   i1a   = (const int*)d_in[7];
    const int*   i1b   = (const int*)d_in[8];
    const int*   i2    = (const int*)d_in[9];
    float* out = (float*)d_out;

    cudaFuncSetAttribute(k2m_gemm, cudaFuncAttributeMaxDynamicSharedMemorySize, K2M_SMEM);

    k1_gemm<<<dim3(16, SPLITK), 256>>>(q, k, Wq, Wk);        // launch 1
    k1b_norm<<<8, 256>>>(out);                                // launch 2
    k2m_gemm<<<dim3(1024, 2), 256, K2M_SMEM>>>(queue, out);   // launch 3
    k3_topk<<<256, 512>>>(out);                               // launch 4 <- ncu
    k4_mix<<<256, 256>>>(queue, alpha, beta, i1a, i1b, i2, out);
    if (out_size > B_ * LD_) k_tail<<<1, 256>>>(out, out_size);
}

// round 17
// speedup vs baseline: 1.4536x; 1.0477x over previous
#include <cuda_runtime.h>
#include <cuda_bf16.h>
#include <cuda_fp16.h>
#include <cstdint>
#include <cstring>

#define B_    256
#define IND   2048
#define D_    128
#define KQ    65536
#define LD_   65569              /* 1 + K + S1 + S2 */
#define INV_T (1.0f/0.07f)
#define LO_SCALE 2048.0f
#define INV_LO   (1.0f/2048.0f)
#define SPLITK 8
#define NC64  1024               /* 64-wide chunks per row */

// ---------------- device scratch (no allocation allowed) -------------------
__device__ __align__(16) float g_pq[SPLITK * B_ * D_];
__device__ __align__(16) float g_pk[SPLITK * B_ * D_];
__device__ __align__(16) float g_outq[B_ * D_];          // normalized out_q
__device__ __align__(16) unsigned short g_ah[B_ * D_];   // fp16 hi of out_q
__device__ __align__(16) unsigned short g_as[B_ * D_];   // fp16 lo*2048 of out_q
__device__ __align__(16) unsigned g_cmaxu[B_ * NC64];    // fkey of per-64chunk max
__device__ int g_hard[B_ * 32];
__device__ unsigned g_dummy[1];

__device__ __forceinline__ unsigned fkey(float f) {
    unsigned u = __float_as_uint(f);
    return (u >> 31) ? ~u : (u | 0x80000000u);
}
__device__ __forceinline__ uint32_t smem_u32(const void* p) {
    uint32_t a;
    asm("{ .reg .u64 t; cvta.to.shared.u64 t, %1; cvt.u32.u64 %0, t; }" : "=r"(a) : "l"(p));
    return a;
}
__device__ __forceinline__ void ldsm4(uint32_t* r, uint32_t a) {
    asm volatile("ldmatrix.sync.aligned.m8n8.x4.shared.b16 {%0,%1,%2,%3}, [%4];"
                 : "=r"(r[0]), "=r"(r[1]), "=r"(r[2]), "=r"(r[3]) : "r"(a));
}
__device__ __forceinline__ void mma_f16(float* c, const uint32_t* a, uint32_t b0, uint32_t b1) {
    asm volatile(
        "mma.sync.aligned.m16n8k16.row.col.f32.f16.f16.f32 "
        "{%0,%1,%2,%3}, {%4,%5,%6,%7}, {%8,%9}, {%0,%1,%2,%3};"
        : "+f"(c[0]), "+f"(c[1]), "+f"(c[2]), "+f"(c[3])
        : "r"(a[0]), "r"(a[1]), "r"(a[2]), "r"(a[3]), "r"(b0), "r"(b1));
}

// ---------------- k1: encoder GEMMs, split-K=8, LDS.128 reads --------------
__global__ void k1_gemm(const float* __restrict__ q, const float* __restrict__ kk,
                        const float* __restrict__ Wq, const float* __restrict__ Wk) {
    __shared__ __align__(16) float qs[16][32];
    __shared__ __align__(16) float ks[16][32];
    const float C0 = 0.999f, C1 = 1.0f - 0.999f;
    int t = threadIdx.x;
    int c = t & 127, h = t >> 7;
    int rb = blockIdx.x * 16;
    int k0 = blockIdx.y * (IND / SPLITK);

    float aq[8], ak[8];
    #pragma unroll
    for (int j = 0; j < 8; j++) { aq[j] = 0.f; ak[j] = 0.f; }

    for (int kc = 0; kc < IND / SPLITK; kc += 32) {
        __syncthreads();
        #pragma unroll
        for (int e = 0; e < 2; e++) {
            int id = t + e * 256;
            int r = id >> 5, i = id & 31;
            qs[r][i] = q [(size_t)(rb + r) * IND + k0 + kc + i];
            ks[r][i] = kk[(size_t)(rb + r) * IND + k0 + kc + i];
        }
        __syncthreads();
        #pragma unroll
        for (int u0 = 0; u0 < 32; u0 += 4) {
            float wq[4], wm[4];
            #pragma unroll
            for (int u = 0; u < 4; u++) {
                float a = Wq[(size_t)(k0 + kc + u0 + u) * D_ + c];
                float b = Wk[(size_t)(k0 + kc + u0 + u) * D_ + c];
                wq[u] = a;
                wm[u] = C0 * b + C1 * a;
            }
            #pragma unroll
            for (int j = 0; j < 8; j++) {
                float4 qv = *(const float4*)&qs[h * 8 + j][u0];
                float4 kv = *(const float4*)&ks[h * 8 + j][u0];
                aq[j] = fmaf(qv.x, wq[0], fmaf(qv.y, wq[1], fmaf(qv.z, wq[2], fmaf(qv.w, wq[3], aq[j]))));
                ak[j] = fmaf(kv.x, wm[0], fmaf(kv.y, wm[1], fmaf(kv.z, wm[2], fmaf(kv.w, wm[3], ak[j]))));
            }
        }
    }
    int sk = blockIdx.y;
    #pragma unroll
    for (int j = 0; j < 8; j++) {
        int r = rb + h * 8 + j;
        g_pq[((size_t)sk * B_ + r) * D_ + c] = aq[j];
        g_pk[((size_t)sk * B_ + r) * D_ + c] = ak[j];
    }
}

// ---------------- k1b: reduce, normalize, pos logit, fp16 hi/lo split ------
__global__ void k1b_norm(float* __restrict__ out) {
    int t = threadIdx.x, lane = t & 31, w = t >> 5;
    int rb = blockIdx.x * 32;
    for (int rr = 0; rr < 4; rr++) {
        int r = rb + rr * 8 + w;
        float4 q4 = make_float4(0.f, 0.f, 0.f, 0.f);
        float4 k4 = make_float4(0.f, 0.f, 0.f, 0.f);
        #pragma unroll
        for (int s = 0; s < SPLITK; s++) {
            float4 a = *(const float4*)&g_pq[((size_t)s * B_ + r) * D_ + lane * 4];
            float4 b = *(const float4*)&g_pk[((size_t)s * B_ + r) * D_ + lane * 4];
            q4.x += a.x; q4.y += a.y; q4.z += a.z; q4.w += a.w;
            k4.x += b.x; k4.y += b.y; k4.z += b.z; k4.w += b.w;
        }
        float s1 = q4.x*q4.x + q4.y*q4.y + q4.z*q4.z + q4.w*q4.w;
        float s2 = k4.x*k4.x + k4.y*k4.y + k4.z*k4.z + k4.w*k4.w;
        float s3 = q4.x*k4.x + q4.y*k4.y + q4.z*k4.z + q4.w*k4.w;
        #pragma unroll
        for (int o = 16; o; o >>= 1) {
            s1 += __shfl_xor_sync(0xffffffffu, s1, o);
            s2 += __shfl_xor_sync(0xffffffffu, s2, o);
            s3 += __shfl_xor_sync(0xffffffffu, s3, o);
        }
        float invq = 1.f / fmaxf(sqrtf(s1), 1e-12f);
        float invk = 1.f / fmaxf(sqrtf(s2), 1e-12f);
        float vs[4] = {q4.x * invq, q4.y * invq, q4.z * invq, q4.w * invq};
        *(float4*)&g_outq[(size_t)r * D_ + lane * 4] = make_float4(vs[0], vs[1], vs[2], vs[3]);
        unsigned hs[4], ls[4];
        #pragma unroll
        for (int j = 0; j < 4; j++) {
            __half hb = __float2half_rn(vs[j]);
            float lo = (vs[j] - __half2float(hb)) * LO_SCALE;
            hs[j] = (unsigned)__half_as_ushort(hb);
            ls[j] = (unsigned)__half_as_ushort(__float2half_rn(lo));
        }
        ((uint2*)g_ah)[r * 32 + lane] = make_uint2(hs[0] | (hs[1] << 16), hs[2] | (hs[3] << 16));
        ((uint2*)g_as)[r * 32 + lane] = make_uint2(ls[0] | (ls[1] << 16), ls[2] | (ls[3] << 16));
        if (lane == 0) out[(size_t)r * LD_] = s3 * invq * invk * INV_T;
    }
}

// ---------------- k_pos3: no-op spacer so ncu (-s 5) captures k2f ----------
__global__ void k_pos3() { if (threadIdx.x == 0) g_dummy[0] = 0u; }

// ---------------- k2f: HMMA fp16 2-term GEMM 256x65536x128 -----------------
// logits = Ah*Bh + (Al*2048)*Bh * (1/2048)  (= A*Bh exactly; only B-trunc err)
// grid (1024 N-chunks of 64, 2 M-tiles of 128). Block 256 thr = 8 warps,
// warp grid 4(M)x2(N), warp tile 32x32. smem XOR-swizzled, conflict-free.
#define AH_O 0
#define AS_O 32768
#define BH_O 65536
#define K2F_SMEM (65536 + 16384)      /* 80 KB */
#define STG_W 66

__global__ void __launch_bounds__(256, 2)
k2f_gemm(const float* __restrict__ queue, float* __restrict__ out) {
    extern __shared__ __align__(16) char smc[];
    int t = threadIdx.x, lane = t & 31, w = t >> 5;
    int wm = w & 3, wn = w >> 2;
    int ci = blockIdx.x, mt = blockIdx.y;
    int nb = ci * 64;

    // ---- load A halves (fp16 in gmem) into swizzled smem ----
    #pragma unroll
    for (int it = 0; it < 8; it++) {
        int cid = t + it * 256;                 // 2048 16B chunks
        int r = cid >> 4, c = cid & 15;
        uint32_t dst = (uint32_t)(r * 256 + ((c ^ (r & 7)) << 4));
        int gi = (mt * 128 + r) * 16 + c;
        *(uint4*)(smc + AH_O + dst) = ((const uint4*)g_ah)[gi];
        *(uint4*)(smc + AS_O + dst) = ((const uint4*)g_as)[gi];
    }
    // ---- load B tile (queue fp32 -> fp16 hi only) ----
    #pragma unroll
    for (int it = 0; it < 8; it++) {
        int cid = t + it * 256;                 // 2048 float4s (64 x 32)
        int n = cid >> 5, c4 = cid & 31;
        float4 v = *(const float4*)(queue + (size_t)(nb + n) * D_ + c4 * 4);
        unsigned h0 = (unsigned)__half_as_ushort(__float2half_rn(v.x));
        unsigned h1 = (unsigned)__half_as_ushort(__float2half_rn(v.y));
        unsigned h2 = (unsigned)__half_as_ushort(__float2half_rn(v.z));
        unsigned h3 = (unsigned)__half_as_ushort(__float2half_rn(v.w));
        int c = c4 >> 1;
        uint32_t dst = (uint32_t)(n * 256 + ((c ^ (n & 7)) << 4) + (c4 & 1) * 8);
        *(uint2*)(smc + BH_O + dst) = make_uint2(h0 | (h1 << 16), h2 | (h3 << 16));
    }
    __syncthreads();

    uint32_t ah = smem_u32(smc + AH_O), as = smem_u32(smc + AS_O);
    uint32_t bh = smem_u32(smc + BH_O);

    float acc1[2][4][4], acc2[2][4][4];
    #pragma unroll
    for (int mi = 0; mi < 2; mi++)
        #pragma unroll
        for (int ni = 0; ni < 4; ni++)
            #pragma unroll
            for (int j = 0; j < 4; j++) { acc1[mi][ni][j] = 0.f; acc2[mi][ni][j] = 0.f; }

    int l15 = lane & 15, sx = lane & 7, khalf = lane >> 4;

    #pragma unroll
    for (int ks = 0; ks < 8; ks++) {
        int kc = ks * 2 + khalf;
        uint32_t Ah[2][4], As[2][4], Bh[2][4];
        #pragma unroll
        for (int mi = 0; mi < 2; mi++) {
            uint32_t off = (uint32_t)((wm * 32 + mi * 16 + l15) * 256 + ((kc ^ sx) << 4));
            ldsm4(Ah[mi], ah + off);
            ldsm4(As[mi], as + off);
        }
        #pragma unroll
        for (int bi = 0; bi < 2; bi++) {
            uint32_t off = (uint32_t)((wn * 32 + bi * 16 + l15) * 256 + ((kc ^ sx) << 4));
            ldsm4(Bh[bi], bh + off);
        }
        #pragma unroll
        for (int mi = 0; mi < 2; mi++)
            #pragma unroll
            for (int ni = 0; ni < 4; ni++) {
                int bi = ni >> 1, j = ni & 1;
                mma_f16(acc1[mi][ni], Ah[mi], Bh[bi][j], Bh[bi][j + 2]);
                mma_f16(acc2[mi][ni], As[mi], Bh[bi][j], Bh[bi][j + 2]);
            }
    }
    __syncthreads();                            // done reading A/B smem

    // ---- stage combined result (stride-66), coalesced stores + cmax ----
    float* stage = (float*)smc;
    #pragma unroll
    for (int mi = 0; mi < 2; mi++)
        #pragma unroll
        for (int ni = 0; ni < 4; ni++) {
            int row = wm * 32 + mi * 16 + (lane >> 2);
            int col = wn * 32 + ni * 8 + (lane & 3) * 2;
            float c0 = (acc1[mi][ni][0] + acc2[mi][ni][0] * INV_LO) * INV_T;
            float c1 = (acc1[mi][ni][1] + acc2[mi][ni][1] * INV_LO) * INV_T;
            float c2 = (acc1[mi][ni][2] + acc2[mi][ni][2] * INV_LO) * INV_T;
            float c3 = (acc1[mi][ni][3] + acc2[mi][ni][3] * INV_LO) * INV_T;
            *(float2*)&stage[row * STG_W + col] = make_float2(c0, c1);
            *(float2*)&stage[(row + 8) * STG_W + col] = make_float2(c2, c3);
        }
    __syncthreads();

    #pragma unroll 2
    for (int rr = 0; rr < 16; rr++) {
        int row = w * 16 + rr;
        float v0 = stage[row * STG_W + lane];
        float v1 = stage[row * STG_W + 32 + lane];
        size_t gb = (size_t)(mt * 128 + row) * LD_ + 1 + nb;
        out[gb + lane]      = v0;
        out[gb + 32 + lane] = v1;
        float m0 = fmaxf(v0, v1);
        #pragma unroll
        for (int o = 16; o; o >>= 1)
            m0 = fmaxf(m0, __shfl_xor_sync(0xffffffffu, m0, o));
        if (lane == 0)
            g_cmaxu[(size_t)(mt * 128 + row) * NC64 + ci] = fkey(m0);
    }
}

// ---------------- k3: exact top-32, radix-select threshold -----------------
#define CHCAP 512
#define CCAP  2048

__global__ void __launch_bounds__(512)
k3_topk(const float* __restrict__ out) {
    __shared__ unsigned bitcnt[32];
    __shared__ int chl[CHCAP];
    __shared__ unsigned long long cand[CCAP];
    __shared__ unsigned s_nch, s_nc;
    int t = threadIdx.x, lane = t & 31, w = t >> 5;
    int r = blockIdx.x;
    const float* row = out + (size_t)r * LD_ + 1;

    unsigned ka = g_cmaxu[(size_t)r * NC64 + t];
    unsigned kb = g_cmaxu[(size_t)r * NC64 + 512 + t];
    if (t < 32) bitcnt[t] = 0;
    if (t == 0) { s_nch = 0; s_nc = 0; }
    __syncthreads();

    unsigned prefix = 0;
    #pragma unroll 1
    for (int b = 31; b >= 0; b--) {
        unsigned cv = prefix | (1u << b);
        int c = (int)(ka >= cv) + (int)(kb >= cv);
        #pragma unroll
        for (int o = 16; o; o >>= 1) c += __shfl_xor_sync(0xffffffffu, c, o);
        if (lane == 0 && c) atomicAdd(&bitcnt[b], (unsigned)c);
        __syncthreads();
        if (bitcnt[b] >= 32u) prefix = cv;
    }
    unsigned T = prefix;

    if (ka >= T) {
        unsigned p = atomicAdd(&s_nch, 1u);
        if (p < CHCAP) chl[p] = t;
    }
    if (kb >= T) {
        unsigned p = atomicAdd(&s_nch, 1u);
        if (p < CHCAP) chl[p] = 512 + t;
    }
    __syncthreads();

    if (s_nch <= CHCAP) {
        int nch = (int)s_nch;
        for (int cidx = w; cidx < nch; cidx += 16) {
            int cbase = chl[cidx] * 64;
            #pragma unroll
            for (int e = 0; e < 2; e++) {
                int j = cbase + lane * 2 + e;
                unsigned fk = fkey(row[j]);
                if (fk >= T) {
                    unsigned p = atomicAdd(&s_nc, 1u);
                    if (p < CCAP)
                        cand[p] = ((unsigned long long)fk << 32) | (unsigned)(~(unsigned)j);
                }
            }
        }
    } else {
        for (int j = t; j < KQ; j += 512) {
            unsigned fk = fkey(row[j]);
            if (fk >= T) {
                unsigned p = atomicAdd(&s_nc, 1u);
                if (p < CCAP)
                    cand[p] = ((unsigned long long)fk << 32) | (unsigned)(~(unsigned)j);
            }
        }
    }
    __syncthreads();
    int n = (int)min(s_nc, (unsigned)CCAP);

    for (int i = t; i < n; i += 512) {
        unsigned long long key = cand[i];
        int rank = 0;
        for (int j = 0; j < n; j++) rank += (cand[j] > key) ? 1 : 0;
        if (rank < 32) g_hard[r * 32 + rank] = (int)(~(unsigned)(key & 0xFFFFFFFFull));
    }
}

// ---------------- k4: mixed hard-negative logits ---------------------------
__global__ void k4_mix(const float* __restrict__ queue, const float* __restrict__ alpha,
                       const float* __restrict__ beta, const int* __restrict__ i1a,
                       const int* __restrict__ i1b, const int* __restrict__ i2,
                       float* __restrict__ out) {
    __shared__ float qsh[D_];
    __shared__ int hsh[32];
    int t = threadIdx.x, lane = t & 31, w = t >> 5;
    int r = blockIdx.x;
    if (t < D_) qsh[t] = g_outq[(size_t)r * D_ + t];
    if (t < 32) hsh[t] = g_hard[r * 32 + t];
    __syncthreads();
    float4 q4 = *(float4*)&qsh[lane * 4];

    #pragma unroll
    for (int e = 0; e < 2; e++) {
        int s = w * 2 + e;
        {
            int g1 = hsh[i1a[r * 16 + s]];
            int g2 = hsh[i1b[r * 16 + s]];
            float a = alpha[r * 16 + s];
            float4 n1 = *(const float4*)(queue + (size_t)g1 * D_ + lane * 4);
            float4 n2 = *(const float4*)(queue + (size_t)g2 * D_ + lane * 4);
            float4 v;
            v.x = a * n1.x + (1.f - a) * n2.x;
            v.y = a * n1.y + (1.f - a) * n2.y;
            v.z = a * n1.z + (1.f - a) * n2.z;
            v.w = a * n1.w + (1.f - a) * n2.w;
            float ss = v.x*v.x + v.y*v.y + v.z*v.z + v.w*v.w;
            float dq = v.x*q4.x + v.y*q4.y + v.z*q4.z + v.w*q4.w;
            #pragma unroll
            for (int o = 16; o; o >>= 1) {
                ss += __shfl_xor_sync(0xffffffffu, ss, o);
                dq += __shfl_xor_sync(0xffffffffu, dq, o);
            }
            if (lane == 0)
                out[(size_t)r * LD_ + 1 + KQ + s] = dq / fmaxf(sqrtf(ss), 1e-12f) * INV_T;
        }
        {
            int g = hsh[i2[r * 16 + s]];
            float bb = beta[r * 16 + s] * 0.5f;
            float4 n1 = *(const float4*)(queue + (size_t)g * D_ + lane * 4);
            float4 v;
            v.x = bb * q4.x + (1.f - bb) * n1.x;
            v.y = bb * q4.y + (1.f - bb) * n1.y;
            v.z = bb * q4.z + (1.f - bb) * n1.z;
            v.w = bb * q4.w + (1.f - bb) * n1.w;
            float ss = v.x*v.x + v.y*v.y + v.z*v.z + v.w*v.w;
            float dq = v.x*q4.x + v.y*q4.y + v.z*q4.z + v.w*q4.w;
            #pragma unroll
            for (int o = 16; o; o >>= 1) {
                ss += __shfl_xor_sync(0xffffffffu, ss, o);
                dq += __shfl_xor_sync(0xffffffffu, dq, o);
            }
            if (lane == 0)
                out[(size_t)r * LD_ + 1 + KQ + 16 + s] = dq / fmaxf(sqrtf(ss), 1e-12f) * INV_T;
        }
    }
}

// ---------------- tail: zero any region past logits ------------------------
__global__ void k_tail(float* __restrict__ out, int total) {
    for (int j = B_ * LD_ + blockIdx.x * blockDim.x + threadIdx.x; j < total;
         j += gridDim.x * blockDim.x)
        out[j] = 0.f;
}

// ---------------- launch ---------------------------------------------------
extern "C" void kernel_launch(void* const* d_in, const int* in_sizes, int n_in,
                              void* d_out, int out_size) {
    const float* q     = (const float*)d_in[0];
    const float* k     = (const float*)d_in[1];
    const float* Wq    = (const float*)d_in[2];
    const float* Wk    = (const float*)d_in[3];
    const float* queue = (const float*)d_in[4];
    const float* alpha = (const float*)d_in[5];
    const float* beta  = (const float*)d_in[6];
    const int*   i1a   = (const int*)d_in[7];
    const int*   i1b   = (const int*)d_in[8];
    const int*   i2    = (const int*)d_in[9];
    float* out = (float*)d_out;

    cudaFuncSetAttribute(k2f_gemm, cudaFuncAttributeMaxDynamicSharedMemorySize, K2F_SMEM);

    k1_gemm<<<dim3(16, SPLITK), 256>>>(q, k, Wq, Wk);        // launch 1
    k1b_norm<<<8, 256>>>(out);                                // launch 2
    k_pos3<<<1, 32>>>();                                      // launch 3 (spacer)
    k2f_gemm<<<dim3(1024, 2), 256, K2F_SMEM>>>(queue, out);   // launch 4 <- ncu
    k3_topk<<<256, 512>>>(out);                               // launch 5
    k4_mix<<<256, 256>>>(queue, alpha, beta, i1a, i1b, i2, out);
    if (out_size > B_ * LD_) k_tail<<<1, 256>>>(out, out_size);
}